// round 13
// baseline (speedup 1.0000x reference)
#include <cuda_runtime.h>
#include <cuda_fp16.h>
#include <math.h>
#include <stdint.h>

// ---------------- Problem constants ----------------
#define BB 8
#define SS 2048
#define EE 768
#define HH 3072          // R*E
#define MM (BB*SS)       // 16384
#define LN_EPS 1e-5f

// fp16 GEMM tiling: CTA 128x256, BK=64, 512 thr, 16 warps of 64x32, 2-stage
#define HBK 64
#define STAGE_A 16384                // 128 rows x 128B
#define STAGE_B 32768                // 256 rows x 128B (NT) / 64 rows x 512B (TR)
#define STAGE_BYTES (STAGE_A + STAGE_B)   // 48KB
#define DSM (2*STAGE_BYTES)               // 96KB dynamic smem

// ---------------- Scratch (device globals; no allocs allowed) ----------------
__device__ __half g_qkv16[5LL*MM*EE];   // 0=q/q2, 1=k, 2=v, 3=k2, 4=v2
__device__ __half g_x16[MM*EE];
__device__ __half g_kv16[MM*EE];
__device__ __half g_x1h[MM*EE];
__device__ __half g_x2h[MM*EE];
__device__ __half g_hh16[(long long)MM*HH];
__device__ __half g_p16[(long long)BB*SS*SS];
__device__ __half g_t16[MM*EE];
__device__ __half g_wt16[6*EE*EE + 2*EE*HH];  // wqT,wkT,wvT,wk2T,wv2T,wq2T,w1T,w2T
__device__ float  g_x1[MM*EE];
__device__ float  g_x2[MM*EE];

// ---------------- Reductions ----------------
__device__ __forceinline__ float warpSum(float v) {
    #pragma unroll
    for (int o = 16; o > 0; o >>= 1) v += __shfl_xor_sync(0xffffffffu, v, o);
    return v;
}
__device__ __forceinline__ float warpMax(float v) {
    #pragma unroll
    for (int o = 16; o > 0; o >>= 1) v = fmaxf(v, __shfl_xor_sync(0xffffffffu, v, o));
    return v;
}
__device__ float blockSum(float v) {
    __shared__ float sh[32];
    int lane = threadIdx.x & 31, w = threadIdx.x >> 5;
    v = warpSum(v);
    if (lane == 0) sh[w] = v;
    __syncthreads();
    int nw = (blockDim.x + 31) >> 5;
    float r = (threadIdx.x < nw) ? sh[threadIdx.x] : 0.f;
    if (w == 0) r = warpSum(r);
    if (threadIdx.x == 0) sh[0] = r;
    __syncthreads();
    r = sh[0];
    __syncthreads();
    return r;
}
__device__ float blockMax(float v) {
    __shared__ float sh[32];
    int lane = threadIdx.x & 31, w = threadIdx.x >> 5;
    v = warpMax(v);
    if (lane == 0) sh[w] = v;
    __syncthreads();
    int nw = (blockDim.x + 31) >> 5;
    float r = (threadIdx.x < nw) ? sh[threadIdx.x] : -INFINITY;
    if (w == 0) r = warpMax(r);
    if (threadIdx.x == 0) sh[0] = r;
    __syncthreads();
    r = sh[0];
    __syncthreads();
    return r;
}

// ---------------- PTX helpers ----------------
__device__ __forceinline__ void cp16(uint32_t dst, const void* src) {
    asm volatile("cp.async.cg.shared.global [%0], [%1], 16;\n" :: "r"(dst), "l"(src));
}
__device__ __forceinline__ void cp_commit() { asm volatile("cp.async.commit_group;\n"); }
__device__ __forceinline__ void cp_wait0()  { asm volatile("cp.async.wait_group 0;\n"); }
__device__ __forceinline__ void cp_wait1()  { asm volatile("cp.async.wait_group 1;\n"); }

__device__ __forceinline__ void mma_f16(float* d, const uint32_t* a,
                                        const uint32_t* b, const float* c) {
    asm volatile(
        "mma.sync.aligned.m16n8k16.row.col.f32.f16.f16.f32 "
        "{%0,%1,%2,%3}, {%4,%5,%6,%7}, {%8,%9}, {%10,%11,%12,%13};\n"
        : "=f"(d[0]), "=f"(d[1]), "=f"(d[2]), "=f"(d[3])
        : "r"(a[0]), "r"(a[1]), "r"(a[2]), "r"(a[3]),
          "r"(b[0]), "r"(b[1]),
          "f"(c[0]), "f"(c[1]), "f"(c[2]), "f"(c[3]));
}
__device__ __forceinline__ void ldsm4(uint32_t* r, uint32_t addr) {
    asm volatile("ldmatrix.sync.aligned.m8n8.x4.shared.b16 {%0,%1,%2,%3}, [%4];\n"
        : "=r"(r[0]), "=r"(r[1]), "=r"(r[2]), "=r"(r[3]) : "r"(addr));
}
__device__ __forceinline__ void ldsm4t(uint32_t* r, uint32_t addr) {
    asm volatile("ldmatrix.sync.aligned.m8n8.x4.trans.shared.b16 {%0,%1,%2,%3}, [%4];\n"
        : "=r"(r[0]), "=r"(r[1]), "=r"(r[2]), "=r"(r[3]) : "r"(addr));
}

// ---------------- fp16 GEMM body (CTA 128x256, 2-stage cp.async) ------------
// NT (BTRANS=0): C[M,N] = A[M,K] @ B[N,K]^T ; btrans (BTRANS=1): B stored [K,N].
// A smem: 128 rows x 64 halves (128B/row), chunk c of row m at (c ^ (m&7)).
// B NT smem: 256 rows x 128B (rows = n), same per-row swizzle.
// B TR smem: 64 k-rows x 256 halves (512B/row), chunk nc of row k at (nc^(k&7)).
template<int BTRANS, int CHALF>
__device__ void hg_body(const __half* __restrict__ A, const __half* __restrict__ B,
                        const float* __restrict__ bias, void* __restrict__ Cv,
                        int N, int K, int rowStart, int colStart, int Keff,
                        float alpha, int relu)
{
    extern __shared__ char dynsm[];
    uint32_t smBase = (uint32_t)__cvta_generic_to_shared(dynsm);

    int tid = threadIdx.x, lane = tid & 31, wid = tid >> 5;
    int wm = (wid >> 3) * 64, wn = (wid & 7) * 32;   // 2 x 8 warp grid
    int g = lane >> 2, tg = lane & 3;
    int T = Keff / HBK;

    auto loadTile = [&](int kt, int s) {
        uint32_t aB = smBase + s * STAGE_BYTES;
        uint32_t bB = aB + STAGE_A;
        #pragma unroll
        for (int i = 0; i < 2; i++) {            // A: 1024 chunks of 16B
            int idx = tid + i * 512;
            int m = idx >> 3, c = idx & 7;
            cp16(aB + m * 128 + ((c ^ (m & 7)) << 4),
                 &A[(long long)(rowStart + m) * K + kt + c * 8]);
        }
        if (!BTRANS) {
            #pragma unroll
            for (int i = 0; i < 4; i++) {        // B: 2048 chunks of 16B
                int idx = tid + i * 512;
                int n = idx >> 3, c = idx & 7;
                cp16(bB + n * 128 + ((c ^ (n & 7)) << 4),
                     &B[(long long)(colStart + n) * K + kt + c * 8]);
            }
        } else {
            #pragma unroll
            for (int i = 0; i < 4; i++) {        // B: 64 k-rows x 32 chunks
                int idx = tid + i * 512;
                int k = idx >> 5, nc = idx & 31;
                cp16(bB + k * 512 + ((nc ^ (k & 7)) << 4),
                     &B[(long long)(kt + k) * N + colStart + nc * 8]);
            }
        }
        cp_commit();
    };

    float acc[4][4][4] = {};
    loadTile(0, 0);
    int buf = 0;
    for (int it = 0; it < T; it++) {
        if (it + 1 < T) { loadTile((it + 1) * HBK, buf ^ 1); cp_wait1(); }
        else cp_wait0();
        __syncthreads();

        uint32_t aT = smBase + buf * STAGE_BYTES;
        uint32_t bT = aT + STAGE_A;
        #pragma unroll
        for (int ks = 0; ks < 4; ks++) {
            uint32_t afr[4][4], bfr[4][2];
            #pragma unroll
            for (int mi = 0; mi < 4; mi++) {
                int m = wm + mi * 16 + (lane & 15);
                int c = 2 * ks + (lane >> 4);
                ldsm4(afr[mi], aT + m * 128 + ((c ^ (m & 7)) << 4));
            }
            if (!BTRANS) {
                #pragma unroll
                for (int h = 0; h < 2; h++) {
                    int n = wn + h * 16 + (lane & 7) + ((lane >> 4) & 1) * 8;
                    int c = 2 * ks + ((lane >> 3) & 1);
                    ldsm4(&bfr[2 * h][0], bT + n * 128 + ((c ^ (n & 7)) << 4));
                }
            } else {
                #pragma unroll
                for (int h = 0; h < 2; h++) {
                    int k = ks * 16 + (lane & 7) + ((lane >> 3) & 1) * 8;
                    int nc = (wn >> 3) + h * 2 + ((lane >> 4) & 1);
                    ldsm4t(&bfr[2 * h][0], bT + k * 512 + ((nc ^ (k & 7)) << 4));
                }
            }
            #pragma unroll
            for (int mi = 0; mi < 4; mi++)
                #pragma unroll
                for (int ni = 0; ni < 4; ni++)
                    mma_f16(acc[mi][ni], afr[mi], bfr[ni], acc[mi][ni]);
        }
        __syncthreads();
        buf ^= 1;
    }

    // Epilogue
    #pragma unroll
    for (int mi = 0; mi < 4; mi++) {
        int row0 = rowStart + wm + mi * 16 + g;
        #pragma unroll
        for (int ni = 0; ni < 4; ni++) {
            int col = colStart + wn + ni * 8 + tg * 2;
            float e[4];
            #pragma unroll
            for (int j = 0; j < 4; j++) e[j] = acc[mi][ni][j] * alpha;
            if (bias) {
                float b0 = bias[col], b1 = bias[col + 1];
                e[0] += b0; e[1] += b1; e[2] += b0; e[3] += b1;
            }
            if (relu) {
                #pragma unroll
                for (int j = 0; j < 4; j++) e[j] = fmaxf(e[j], 0.f);
            }
            if (CHALF) {
                __half* C = (__half*)Cv;
                *reinterpret_cast<__half2*>(&C[(long long)row0 * N + col]) =
                    __floats2half2_rn(e[0], e[1]);
                *reinterpret_cast<__half2*>(&C[(long long)(row0 + 8) * N + col]) =
                    __floats2half2_rn(e[2], e[3]);
            } else {
                float* C = (float*)Cv;
                *reinterpret_cast<float2*>(&C[(long long)row0 * N + col]) =
                    make_float2(e[0], e[1]);
                *reinterpret_cast<float2*>(&C[(long long)(row0 + 8) * N + col]) =
                    make_float2(e[2], e[3]);
            }
        }
    }
}

template<int BTRANS, int CHALF>
__global__ __launch_bounds__(512, 1)
void hgemm_k(const __half* __restrict__ A, const __half* __restrict__ B,
             const float* __restrict__ bias, void* __restrict__ C,
             int N, int K, long long sA, long long sB, long long sC,
             float alpha, int relu, int causalSkip, int causalKlim)
{
    int rowStart = blockIdx.y * 128;
    int colStart = blockIdx.x * 256;
    if (causalSkip && rowStart + 127 < colStart) return;
    int z = blockIdx.z;
    A += (long long)z * sA;
    B += (long long)z * sB;
    C = (void*)((char*)C + (long long)z * sC * (CHALF ? 2 : 4));
    int Keff = K;
    if (causalKlim) { int kl = rowStart + 128; if (kl < Keff) Keff = kl; }
    hg_body<BTRANS, CHALF>(A, B, bias, C, N, K, rowStart, colStart, Keff, alpha, relu);
}

// fused 5-way projection: z in {q,k,v,k2,v2}; A = x16 (z<3) else kv16.
__global__ __launch_bounds__(512, 1)
void hg_proj5(const __half* __restrict__ x16, const __half* __restrict__ kv16,
              const __half* __restrict__ wt,
              const float* __restrict__ b0, const float* __restrict__ b1,
              const float* __restrict__ b2, const float* __restrict__ b3,
              const float* __restrict__ b4, __half* __restrict__ qkv)
{
    int z = blockIdx.z;
    const __half* A = (z < 3) ? x16 : kv16;
    const __half* B = wt + (long long)z * EE * EE;
    const float* bias = (z == 0) ? b0 : (z == 1) ? b1 : (z == 2) ? b2 : (z == 3) ? b3 : b4;
    __half* C = qkv + (long long)z * MM * EE;
    hg_body<0, 1>(A, B, bias, C, EE, EE, blockIdx.y * 128, blockIdx.x * 256, EE,
                  1.0f, 0);
}

// ---------------- fp32 -> fp16 convert (two tensors in one launch) ----------
__global__ void cvt2_h(const float4* __restrict__ S0, const float4* __restrict__ S1,
                       __half2* __restrict__ D0, __half2* __restrict__ D1, int n4)
{
    const float4* S = blockIdx.y ? S1 : S0;
    __half2* D = blockIdx.y ? D1 : D0;
    int i = blockIdx.x * blockDim.x + threadIdx.x;
    if (i < n4) {
        float4 v = S[i];
        D[2 * i]     = __floats2half2_rn(v.x, v.y);
        D[2 * i + 1] = __floats2half2_rn(v.z, v.w);
    }
}

// ---------------- Weight transpose+convert: D[C,R]h = S[R,C]^T ----------------
__global__ void transp_h(const float* __restrict__ S, __half* __restrict__ D,
                         int R, int C)
{
    __shared__ float tb[32][33];
    int r0 = blockIdx.x * 32, c0 = blockIdx.y * 32;
    int tx = threadIdx.x & 31, ty = threadIdx.x >> 5;
    #pragma unroll
    for (int i = 0; i < 32; i += 8)
        tb[ty + i][tx] = S[(long long)(r0 + ty + i) * C + c0 + tx];
    __syncthreads();
    #pragma unroll
    for (int i = 0; i < 32; i += 8)
        D[(long long)(c0 + ty + i) * R + r0 + tx] = __float2half_rn(tb[tx][ty + i]);
}
__global__ void transp6_h(const float* __restrict__ s0, const float* __restrict__ s1,
                          const float* __restrict__ s2, const float* __restrict__ s3,
                          const float* __restrict__ s4, const float* __restrict__ s5,
                          __half* __restrict__ D)
{
    __shared__ float tb[32][33];
    int z = blockIdx.z;
    const float* S = (z==0)?s0:(z==1)?s1:(z==2)?s2:(z==3)?s3:(z==4)?s4:s5;
    __half* Dz = D + (long long)z * EE * EE;
    int r0 = blockIdx.x * 32, c0 = blockIdx.y * 32;
    int tx = threadIdx.x & 31, ty = threadIdx.x >> 5;
    #pragma unroll
    for (int i = 0; i < 32; i += 8)
        tb[ty + i][tx] = S[(long long)(r0 + ty + i) * EE + c0 + tx];
    __syncthreads();
    #pragma unroll
    for (int i = 0; i < 32; i += 8)
        Dz[(long long)(c0 + ty + i) * EE + r0 + tx] = __float2half_rn(tb[tx][ty + i]);
}

// ---------------- Softmax: fp16 scores -> fp16 probs, in place --------------
// 256 thr, 8 halves each. Causal: skip loads/stores beyond padded diag block.
__global__ void softmax16(__half* __restrict__ P, int S, int causal)
{
    long long z = blockIdx.y;
    int i = blockIdx.x;
    __half* row = P + (z * S + i) * (long long)S;
    int len = causal ? (i + 1) : S;
    int lenPad = causal ? (((i >> 7) + 1) << 7) : S;

    int c0 = threadIdx.x * 8;
    float va[8];
    if (c0 < lenPad) {
        uint4 raw = *reinterpret_cast<const uint4*>(&row[c0]);
        __half2 hp[4];
        hp[0] = *reinterpret_cast<__half2*>(&raw.x);
        hp[1] = *reinterpret_cast<__half2*>(&raw.y);
        hp[2] = *reinterpret_cast<__half2*>(&raw.z);
        hp[3] = *reinterpret_cast<__half2*>(&raw.w);
        #pragma unroll
        for (int p = 0; p < 4; p++) {
            float2 f = __half22float2(hp[p]);
            va[2 * p] = f.x; va[2 * p + 1] = f.y;
        }
    } else {
        #pragma unroll
        for (int e = 0; e < 8; e++) va[e] = -INFINITY;
    }
    float mx = -INFINITY;
    #pragma unroll
    for (int e = 0; e < 8; e++) {
        if (c0 + e >= len) va[e] = -INFINITY;
        mx = fmaxf(mx, va[e]);
    }
    mx = blockMax(mx);

    float s = 0.f;
    #pragma unroll
    for (int e = 0; e < 8; e++) { va[e] = expf(va[e] - mx); s += va[e]; }
    s = blockSum(s);
    float inv = 1.f / s;
    #pragma unroll
    for (int e = 0; e < 8; e++) va[e] *= inv;

    if (c0 < lenPad) {
        uint4 o;
        __half2 o0 = __floats2half2_rn(va[0], va[1]);
        __half2 o1 = __floats2half2_rn(va[2], va[3]);
        __half2 o2 = __floats2half2_rn(va[4], va[5]);
        __half2 o3 = __floats2half2_rn(va[6], va[7]);
        o.x = *reinterpret_cast<uint32_t*>(&o0);
        o.y = *reinterpret_cast<uint32_t*>(&o1);
        o.z = *reinterpret_cast<uint32_t*>(&o2);
        o.w = *reinterpret_cast<uint32_t*>(&o3);
        *reinterpret_cast<uint4*>(&row[c0]) = o;
    }
}

// ---------------- Fused residual-add + LayerNorm (192 thr, vectorized) ------
// X residual fp32; Hh (GEMM output) fp16.
__global__ void add_ln(const float* __restrict__ X, const __half* __restrict__ Hh,
                       const float* __restrict__ g, const float* __restrict__ b,
                       float* __restrict__ Y, __half* __restrict__ Yh)
{
    long long row = blockIdx.x;
    const float* x = X + row * EE;
    const __half* h = Hh + row * EE;
    float* y = Y + row * EE;
    int c = threadIdx.x * 4;

    float4 xv = *reinterpret_cast<const float4*>(&x[c]);
    uint2 hu = *reinterpret_cast<const uint2*>(&h[c]);
    float2 h0 = __half22float2(*reinterpret_cast<__half2*>(&hu.x));
    float2 h1 = __half22float2(*reinterpret_cast<__half2*>(&hu.y));
    float v[4] = {xv.x + h0.x, xv.y + h0.y, xv.z + h1.x, xv.w + h1.y};

    float s = v[0] + v[1] + v[2] + v[3];
    s = blockSum(s);
    float mean = s * (1.0f / EE);

    float q = 0.f;
    #pragma unroll
    for (int j = 0; j < 4; j++) { float d = v[j] - mean; q += d * d; }
    q = blockSum(q);
    float inv = rsqrtf(q * (1.0f / EE) + LN_EPS);

    float4 gv = *reinterpret_cast<const float4*>(&g[c]);
    float4 bv = *reinterpret_cast<const float4*>(&b[c]);
    float o[4];
    o[0] = (v[0] - mean) * inv * gv.x + bv.x;
    o[1] = (v[1] - mean) * inv * gv.y + bv.y;
    o[2] = (v[2] - mean) * inv * gv.z + bv.z;
    o[3] = (v[3] - mean) * inv * gv.w + bv.w;
    *reinterpret_cast<float4*>(&y[c]) = make_float4(o[0], o[1], o[2], o[3]);
    if (Yh) {
        __half2 q0 = __floats2half2_rn(o[0], o[1]);
        __half2 q1 = __floats2half2_rn(o[2], o[3]);
        uint2 u;
        u.x = *reinterpret_cast<uint32_t*>(&q0);
        u.y = *reinterpret_cast<uint32_t*>(&q1);
        *reinterpret_cast<uint2*>(&Yh[row * EE + c]) = u;
    }
}

// ---------------- Orchestration ----------------
extern "C" void kernel_launch(void* const* d_in, const int* in_sizes, int n_in,
                              void* d_out, int out_size)
{
    const float* x     = (const float*)d_in[0];
    const float* kv    = (const float*)d_in[1];
    const float* wq_w  = (const float*)d_in[2];
    const float* wq_b  = (const float*)d_in[3];
    const float* wk_w  = (const float*)d_in[4];
    const float* wk_b  = (const float*)d_in[5];
    const float* wv_w  = (const float*)d_in[6];
    const float* wv_b  = (const float*)d_in[7];
    const float* ln1_g = (const float*)d_in[8];
    const float* ln1_b = (const float*)d_in[9];
    const float* wq2_w = (const float*)d_in[10];
    const float* wq2_b = (const float*)d_in[11];
    const float* wk2_w = (const float*)d_in[12];
    const float* wk2_b = (const float*)d_in[13];
    const float* wv2_w = (const float*)d_in[14];
    const float* wv2_b = (const float*)d_in[15];
    const float* ln2_g = (const float*)d_in[16];
    const float* ln2_b = (const float*)d_in[17];
    const float* mlp_w1= (const float*)d_in[18];
    const float* mlp_b1= (const float*)d_in[19];
    const float* mlp_w2= (const float*)d_in[20];
    const float* mlp_b2= (const float*)d_in[21];
    const float* ln3_g = (const float*)d_in[22];
    const float* ln3_b = (const float*)d_in[23];
    float* out = (float*)d_out;

    __half *qkv, *x16, *kv16, *x1h, *x2h, *hh16, *p16, *t16, *wt;
    float *x1, *x2;
    cudaGetSymbolAddress((void**)&qkv,  g_qkv16);
    cudaGetSymbolAddress((void**)&x16,  g_x16);
    cudaGetSymbolAddress((void**)&kv16, g_kv16);
    cudaGetSymbolAddress((void**)&x1h,  g_x1h);
    cudaGetSymbolAddress((void**)&x2h,  g_x2h);
    cudaGetSymbolAddress((void**)&hh16, g_hh16);
    cudaGetSymbolAddress((void**)&p16,  g_p16);
    cudaGetSymbolAddress((void**)&t16,  g_t16);
    cudaGetSymbolAddress((void**)&wt,   g_wt16);
    cudaGetSymbolAddress((void**)&x1,   g_x1);
    cudaGetSymbolAddress((void**)&x2,   g_x2);

    cudaFuncSetAttribute(hgemm_k<0,1>, cudaFuncAttributeMaxDynamicSharedMemorySize, DSM);
    cudaFuncSetAttribute(hgemm_k<1,1>, cudaFuncAttributeMaxDynamicSharedMemorySize, DSM);
    cudaFuncSetAttribute(hg_proj5,     cudaFuncAttributeMaxDynamicSharedMemorySize, DSM);

    __half* q16 = qkv;
    __half* k16 = qkv + 1LL*MM*EE;
    __half* v16 = qkv + 2LL*MM*EE;
    __half* k2  = qkv + 3LL*MM*EE;
    __half* v2  = qkv + 4LL*MM*EE;
    __half* wq2T = wt + 5LL*EE*EE;
    __half* w1T  = wt + 6LL*EE*EE;
    __half* w2T  = wt + 6LL*EE*EE + (long long)EE*HH;

    const float scale = 1.0f / sqrtf((float)EE);
    const long long SE  = (long long)SS * EE;
    const long long SSS = (long long)SS * SS;

    dim3 b512(512), b256(256), b192(192);
    dim3 gProj(EE / 256, MM / 128, 1);       // (3,128)
    dim3 gProj5(EE / 256, MM / 128, 5);      // (3,128,5)
    dim3 gScore(SS / 256, SS / 128, BB);     // (8,16,8)
    dim3 gPV(EE / 256, SS / 128, BB);        // (3,16,8)
    dim3 gMlp1(HH / 256, MM / 128, 1);       // (12,128)
    dim3 gSm(SS, BB);
    dim3 gLn(MM);

    // --- one-time conversions ---
    int n4 = MM * EE / 4;
    cvt2_h<<<dim3((n4 + 255) / 256, 2), b256>>>((const float4*)x, (const float4*)kv,
                                                (__half2*)x16, (__half2*)kv16, n4);
    transp6_h<<<dim3(24, 24, 6), b256>>>(wq_w, wk_w, wv_w, wk2_w, wv2_w, wq2_w, wt);
    transp_h<<<dim3(EE/32, HH/32), b256>>>(mlp_w1, w1T, EE, HH);
    transp_h<<<dim3(HH/32, EE/32), b256>>>(mlp_w2, w2T, HH, EE);

    // --- all 5 input projections in one launch ---
    hg_proj5<<<gProj5, b512, DSM>>>(x16, kv16, wt, wq_b, wk_b, wv_b, wk2_b, wv2_b, qkv);

    // --- causal self-attention (fp16 end-to-end intermediates) ---
    hgemm_k<0,1><<<gScore, b512, DSM>>>(q16, k16, nullptr, p16, SS, EE,
                                        SE, SE, SSS, scale, 0, 1, 0);
    softmax16<<<gSm, b256>>>(p16, SS, 1);
    hgemm_k<1,1><<<gPV, b512, DSM>>>(p16, v16, nullptr, t16, EE, SS,
                                     SSS, SE, SE, 1.0f, 0, 0, 1);
    add_ln<<<gLn, b192>>>(x, t16, ln1_g, ln1_b, x1, x1h);

    // --- cross-attention ---
    hgemm_k<0,1><<<gProj, b512, DSM>>>(x1h, wq2T, wq2_b, q16, EE, EE,
                                       0, 0, 0, 1.0f, 0, 0, 0);
    hgemm_k<0,1><<<gScore, b512, DSM>>>(q16, k2, nullptr, p16, SS, EE,
                                        SE, SE, SSS, scale, 0, 0, 0);
    softmax16<<<gSm, b256>>>(p16, SS, 0);
    hgemm_k<1,1><<<gPV, b512, DSM>>>(p16, v2, nullptr, t16, EE, SS,
                                     SSS, SE, SE, 1.0f, 0, 0, 0);
    add_ln<<<gLn, b192>>>(x1, t16, ln2_g, ln2_b, x2, x2h);

    // --- MLP (ReLU after both linears) ---
    hgemm_k<0,1><<<gMlp1, b512, DSM>>>(x2h, w1T, mlp_b1, hh16, HH, EE,
                                       0, 0, 0, 1.0f, 1, 0, 0);
    hgemm_k<0,1><<<gProj, b512, DSM>>>(hh16, w2T, mlp_b2, t16, EE, HH,
                                       0, 0, 0, 1.0f, 1, 0, 0);
    add_ln<<<gLn, b192>>>(x2, t16, ln3_g, ln3_b, out, nullptr);
}

// round 14
// speedup vs baseline: 1.0808x; 1.0808x over previous
#include <cuda_runtime.h>
#include <cuda_fp16.h>
#include <math.h>
#include <stdint.h>

// ---------------- Problem constants ----------------
#define BB 8
#define SS 2048
#define EE 768
#define HH 3072          // R*E
#define MM (BB*SS)       // 16384
#define LN_EPS 1e-5f

// fp16 GEMM tiling: CTA 128x128, BK=64, 256 thr, 8 warps of 64x32, 2-stage
#define HBK 64
#define STAGE_BYTES 32768            // A 16KB + B 16KB per stage
#define DSM (2*STAGE_BYTES)          // 64KB dynamic smem

// ---------------- Scratch (device globals; no allocs allowed) ----------------
__device__ __half g_qkv16[5LL*MM*EE];   // 0=q/q2, 1=k, 2=v, 3=k2, 4=v2
__device__ __half g_x16[MM*EE];
__device__ __half g_kv16[MM*EE];
__device__ __half g_x1h[MM*EE];
__device__ __half g_x2h[MM*EE];
__device__ __half g_hh16[(long long)MM*HH];
__device__ __half g_p16[(long long)BB*SS*SS];
__device__ __half g_t16[MM*EE];
__device__ __half g_wt16[6*EE*EE + 2*EE*HH];  // wqT,wkT,wvT,wk2T,wv2T,wq2T,w1T,w2T
__device__ float  g_x1[MM*EE];
__device__ float  g_x2[MM*EE];

// ---------------- Reductions ----------------
__device__ __forceinline__ float warpSum(float v) {
    #pragma unroll
    for (int o = 16; o > 0; o >>= 1) v += __shfl_xor_sync(0xffffffffu, v, o);
    return v;
}
__device__ __forceinline__ float warpMax(float v) {
    #pragma unroll
    for (int o = 16; o > 0; o >>= 1) v = fmaxf(v, __shfl_xor_sync(0xffffffffu, v, o));
    return v;
}
__device__ float blockSum(float v) {
    __shared__ float sh[32];
    int lane = threadIdx.x & 31, w = threadIdx.x >> 5;
    v = warpSum(v);
    if (lane == 0) sh[w] = v;
    __syncthreads();
    int nw = (blockDim.x + 31) >> 5;
    float r = (threadIdx.x < nw) ? sh[threadIdx.x] : 0.f;
    if (w == 0) r = warpSum(r);
    if (threadIdx.x == 0) sh[0] = r;
    __syncthreads();
    r = sh[0];
    __syncthreads();
    return r;
}
__device__ float blockMax(float v) {
    __shared__ float sh[32];
    int lane = threadIdx.x & 31, w = threadIdx.x >> 5;
    v = warpMax(v);
    if (lane == 0) sh[w] = v;
    __syncthreads();
    int nw = (blockDim.x + 31) >> 5;
    float r = (threadIdx.x < nw) ? sh[threadIdx.x] : -INFINITY;
    if (w == 0) r = warpMax(r);
    if (threadIdx.x == 0) sh[0] = r;
    __syncthreads();
    r = sh[0];
    __syncthreads();
    return r;
}

// ---------------- PTX helpers ----------------
__device__ __forceinline__ void cp16(uint32_t dst, const void* src) {
    asm volatile("cp.async.cg.shared.global [%0], [%1], 16;\n" :: "r"(dst), "l"(src));
}
__device__ __forceinline__ void cp_commit() { asm volatile("cp.async.commit_group;\n"); }
__device__ __forceinline__ void cp_wait0()  { asm volatile("cp.async.wait_group 0;\n"); }
__device__ __forceinline__ void cp_wait1()  { asm volatile("cp.async.wait_group 1;\n"); }

__device__ __forceinline__ void mma_f16(float* d, const uint32_t* a,
                                        const uint32_t* b, const float* c) {
    asm volatile(
        "mma.sync.aligned.m16n8k16.row.col.f32.f16.f16.f32 "
        "{%0,%1,%2,%3}, {%4,%5,%6,%7}, {%8,%9}, {%10,%11,%12,%13};\n"
        : "=f"(d[0]), "=f"(d[1]), "=f"(d[2]), "=f"(d[3])
        : "r"(a[0]), "r"(a[1]), "r"(a[2]), "r"(a[3]),
          "r"(b[0]), "r"(b[1]),
          "f"(c[0]), "f"(c[1]), "f"(c[2]), "f"(c[3]));
}
__device__ __forceinline__ void ldsm4(uint32_t* r, uint32_t addr) {
    asm volatile("ldmatrix.sync.aligned.m8n8.x4.shared.b16 {%0,%1,%2,%3}, [%4];\n"
        : "=r"(r[0]), "=r"(r[1]), "=r"(r[2]), "=r"(r[3]) : "r"(addr));
}
__device__ __forceinline__ void ldsm4t(uint32_t* r, uint32_t addr) {
    asm volatile("ldmatrix.sync.aligned.m8n8.x4.trans.shared.b16 {%0,%1,%2,%3}, [%4];\n"
        : "=r"(r[0]), "=r"(r[1]), "=r"(r[2]), "=r"(r[3]) : "r"(addr));
}

// ---------------- fp16 GEMM body (2-stage cp.async pipeline) ----------------
// NT (BTRANS=0): C[M,N] = A[M,K] @ B[N,K]^T ; btrans (BTRANS=1): B stored [K,N].
// A smem: 128 rows x 64 halves (128B), 16B chunk c of row m at (c ^ (m&7)).
// B NT smem: same geometry (rows = n). B trans smem: 64 k-rows x 128 halves
// (256B), chunk nc of row k at (nc ^ (k&7)).
template<int BTRANS, int CHALF>
__device__ void hg_body(const __half* __restrict__ A, const __half* __restrict__ B,
                        const float* __restrict__ bias, void* __restrict__ Cv,
                        int N, int K, int rowStart, int colStart, int Keff,
                        float alpha, int relu)
{
    extern __shared__ char dynsm[];
    uint32_t smBase = (uint32_t)__cvta_generic_to_shared(dynsm);

    int tid = threadIdx.x, lane = tid & 31, wid = tid >> 5;
    int wm = (wid >> 2) * 64, wn = (wid & 3) * 32;
    int g = lane >> 2, tg = lane & 3;
    int T = Keff / HBK;

    auto loadTile = [&](int kt, int s) {
        uint32_t aB = smBase + s * STAGE_BYTES;
        uint32_t bB = aB + 16384;
        #pragma unroll
        for (int i = 0; i < 4; i++) {
            int idx = tid + i * 256;             // 1024 chunks
            int m = idx >> 3, c = idx & 7;
            cp16(aB + m * 128 + ((c ^ (m & 7)) << 4),
                 &A[(long long)(rowStart + m) * K + kt + c * 8]);
        }
        if (!BTRANS) {
            #pragma unroll
            for (int i = 0; i < 4; i++) {
                int idx = tid + i * 256;
                int n = idx >> 3, c = idx & 7;
                cp16(bB + n * 128 + ((c ^ (n & 7)) << 4),
                     &B[(long long)(colStart + n) * K + kt + c * 8]);
            }
        } else {
            #pragma unroll
            for (int i = 0; i < 4; i++) {
                int idx = tid + i * 256;
                int k = idx >> 4, nc = idx & 15;
                cp16(bB + k * 256 + ((nc ^ (k & 7)) << 4),
                     &B[(long long)(kt + k) * N + colStart + nc * 8]);
            }
        }
        cp_commit();
    };

    float acc[4][4][4] = {};
    loadTile(0, 0);
    int buf = 0;
    for (int it = 0; it < T; it++) {
        if (it + 1 < T) { loadTile((it + 1) * HBK, buf ^ 1); cp_wait1(); }
        else cp_wait0();
        __syncthreads();

        uint32_t aT = smBase + buf * STAGE_BYTES;
        uint32_t bT = aT + 16384;
        #pragma unroll
        for (int ks = 0; ks < 4; ks++) {
            uint32_t afr[4][4], bfr[4][2];
            #pragma unroll
            for (int mi = 0; mi < 4; mi++) {
                int m = wm + mi * 16 + (lane & 15);
                int c = 2 * ks + (lane >> 4);
                ldsm4(afr[mi], aT + m * 128 + ((c ^ (m & 7)) << 4));
            }
            if (!BTRANS) {
                #pragma unroll
                for (int h = 0; h < 2; h++) {
                    int n = wn + h * 16 + (lane & 7) + ((lane >> 4) & 1) * 8;
                    int c = 2 * ks + ((lane >> 3) & 1);
                    ldsm4(&bfr[2 * h][0], bT + n * 128 + ((c ^ (n & 7)) << 4));
                }
            } else {
                #pragma unroll
                for (int h = 0; h < 2; h++) {
                    int k = ks * 16 + (lane & 7) + ((lane >> 3) & 1) * 8;
                    int nc = (wn >> 3) + h * 2 + ((lane >> 4) & 1);
                    ldsm4t(&bfr[2 * h][0], bT + k * 256 + ((nc ^ (k & 7)) << 4));
                }
            }
            #pragma unroll
            for (int mi = 0; mi < 4; mi++)
                #pragma unroll
                for (int ni = 0; ni < 4; ni++)
                    mma_f16(acc[mi][ni], afr[mi], bfr[ni], acc[mi][ni]);
        }
        __syncthreads();
        buf ^= 1;
    }

    // Epilogue
    #pragma unroll
    for (int mi = 0; mi < 4; mi++) {
        int row0 = rowStart + wm + mi * 16 + g;
        #pragma unroll
        for (int ni = 0; ni < 4; ni++) {
            int col = colStart + wn + ni * 8 + tg * 2;
            float e[4];
            #pragma unroll
            for (int j = 0; j < 4; j++) e[j] = acc[mi][ni][j] * alpha;
            if (bias) {
                float b0 = bias[col], b1 = bias[col + 1];
                e[0] += b0; e[1] += b1; e[2] += b0; e[3] += b1;
            }
            if (relu) {
                #pragma unroll
                for (int j = 0; j < 4; j++) e[j] = fmaxf(e[j], 0.f);
            }
            if (CHALF) {
                __half* C = (__half*)Cv;
                *reinterpret_cast<__half2*>(&C[(long long)row0 * N + col]) =
                    __floats2half2_rn(e[0], e[1]);
                *reinterpret_cast<__half2*>(&C[(long long)(row0 + 8) * N + col]) =
                    __floats2half2_rn(e[2], e[3]);
            } else {
                float* C = (float*)Cv;
                *reinterpret_cast<float2*>(&C[(long long)row0 * N + col]) =
                    make_float2(e[0], e[1]);
                *reinterpret_cast<float2*>(&C[(long long)(row0 + 8) * N + col]) =
                    make_float2(e[2], e[3]);
            }
        }
    }
}

template<int BTRANS, int CHALF>
__global__ __launch_bounds__(256, 2)
void hgemm_k(const __half* __restrict__ A, const __half* __restrict__ B,
             const float* __restrict__ bias, void* __restrict__ C,
             int N, int K, long long sA, long long sB, long long sC,
             float alpha, int relu, int causalSkip, int causalKlim)
{
    int rowStart = blockIdx.y * 128;
    int colStart = blockIdx.x * 128;
    if (causalSkip && rowStart + 127 < colStart) return;
    int z = blockIdx.z;
    A += (long long)z * sA;
    B += (long long)z * sB;
    C = (void*)((char*)C + (long long)z * sC * (CHALF ? 2 : 4));
    int Keff = K;
    if (causalKlim) { int kl = rowStart + 128; if (kl < Keff) Keff = kl; }
    hg_body<BTRANS, CHALF>(A, B, bias, C, N, K, rowStart, colStart, Keff, alpha, relu);
}

// fused 5-way projection: z in {q,k,v,k2,v2}; A = x16 (z<3) else kv16.
__global__ __launch_bounds__(256, 2)
void hg_proj5(const __half* __restrict__ x16, const __half* __restrict__ kv16,
              const __half* __restrict__ wt,
              const float* __restrict__ b0, const float* __restrict__ b1,
              const float* __restrict__ b2, const float* __restrict__ b3,
              const float* __restrict__ b4, __half* __restrict__ qkv)
{
    int z = blockIdx.z;
    const __half* A = (z < 3) ? x16 : kv16;
    const __half* B = wt + (long long)z * EE * EE;
    const float* bias = (z == 0) ? b0 : (z == 1) ? b1 : (z == 2) ? b2 : (z == 3) ? b3 : b4;
    __half* C = qkv + (long long)z * MM * EE;
    hg_body<0, 1>(A, B, bias, C, EE, EE, blockIdx.y * 128, blockIdx.x * 128, EE,
                  1.0f, 0);
}

// ---------------- fp32 -> fp16 convert (two tensors in one launch) ----------
__global__ void cvt2_h(const float4* __restrict__ S0, const float4* __restrict__ S1,
                       __half2* __restrict__ D0, __half2* __restrict__ D1, int n4)
{
    const float4* S = blockIdx.y ? S1 : S0;
    __half2* D = blockIdx.y ? D1 : D0;
    int i = blockIdx.x * blockDim.x + threadIdx.x;
    if (i < n4) {
        float4 v = S[i];
        D[2 * i]     = __floats2half2_rn(v.x, v.y);
        D[2 * i + 1] = __floats2half2_rn(v.z, v.w);
    }
}

// ---------------- Weight transpose+convert: D[C,R]h = S[R,C]^T ----------------
__global__ void transp_h(const float* __restrict__ S, __half* __restrict__ D,
                         int R, int C)
{
    __shared__ float tb[32][33];
    int r0 = blockIdx.x * 32, c0 = blockIdx.y * 32;
    int tx = threadIdx.x & 31, ty = threadIdx.x >> 5;
    #pragma unroll
    for (int i = 0; i < 32; i += 8)
        tb[ty + i][tx] = S[(long long)(r0 + ty + i) * C + c0 + tx];
    __syncthreads();
    #pragma unroll
    for (int i = 0; i < 32; i += 8)
        D[(long long)(c0 + ty + i) * R + r0 + tx] = __float2half_rn(tb[tx][ty + i]);
}
__global__ void transp6_h(const float* __restrict__ s0, const float* __restrict__ s1,
                          const float* __restrict__ s2, const float* __restrict__ s3,
                          const float* __restrict__ s4, const float* __restrict__ s5,
                          __half* __restrict__ D)
{
    __shared__ float tb[32][33];
    int z = blockIdx.z;
    const float* S = (z==0)?s0:(z==1)?s1:(z==2)?s2:(z==3)?s3:(z==4)?s4:s5;
    __half* Dz = D + (long long)z * EE * EE;
    int r0 = blockIdx.x * 32, c0 = blockIdx.y * 32;
    int tx = threadIdx.x & 31, ty = threadIdx.x >> 5;
    #pragma unroll
    for (int i = 0; i < 32; i += 8)
        tb[ty + i][tx] = S[(long long)(r0 + ty + i) * EE + c0 + tx];
    __syncthreads();
    #pragma unroll
    for (int i = 0; i < 32; i += 8)
        Dz[(long long)(c0 + ty + i) * EE + r0 + tx] = __float2half_rn(tb[tx][ty + i]);
}

// ---------------- Softmax: fp16 scores -> fp16 probs, in place --------------
// 256 thr, 8 halves each. Fast-math exp/rcp (probabilities tolerate ~1e-6).
// Causal: skip loads/stores beyond padded diag block.
__global__ void softmax16(__half* __restrict__ P, int S, int causal)
{
    long long z = blockIdx.y;
    int i = blockIdx.x;
    __half* row = P + (z * S + i) * (long long)S;
    int len = causal ? (i + 1) : S;
    int lenPad = causal ? (((i >> 7) + 1) << 7) : S;

    int c0 = threadIdx.x * 8;
    float va[8];
    if (c0 < lenPad) {
        uint4 raw = *reinterpret_cast<const uint4*>(&row[c0]);
        __half2 hp[4];
        hp[0] = *reinterpret_cast<__half2*>(&raw.x);
        hp[1] = *reinterpret_cast<__half2*>(&raw.y);
        hp[2] = *reinterpret_cast<__half2*>(&raw.z);
        hp[3] = *reinterpret_cast<__half2*>(&raw.w);
        #pragma unroll
        for (int p = 0; p < 4; p++) {
            float2 f = __half22float2(hp[p]);
            va[2 * p] = f.x; va[2 * p + 1] = f.y;
        }
    } else {
        #pragma unroll
        for (int e = 0; e < 8; e++) va[e] = -INFINITY;
    }
    float mx = -INFINITY;
    #pragma unroll
    for (int e = 0; e < 8; e++) {
        if (c0 + e >= len) va[e] = -INFINITY;
        mx = fmaxf(mx, va[e]);
    }
    mx = blockMax(mx);

    float s = 0.f;
    #pragma unroll
    for (int e = 0; e < 8; e++) { va[e] = __expf(va[e] - mx); s += va[e]; }
    s = blockSum(s);
    float inv = __fdividef(1.f, s);
    #pragma unroll
    for (int e = 0; e < 8; e++) va[e] *= inv;

    if (c0 < lenPad) {
        uint4 o;
        __half2 o0 = __floats2half2_rn(va[0], va[1]);
        __half2 o1 = __floats2half2_rn(va[2], va[3]);
        __half2 o2 = __floats2half2_rn(va[4], va[5]);
        __half2 o3 = __floats2half2_rn(va[6], va[7]);
        o.x = *reinterpret_cast<uint32_t*>(&o0);
        o.y = *reinterpret_cast<uint32_t*>(&o1);
        o.z = *reinterpret_cast<uint32_t*>(&o2);
        o.w = *reinterpret_cast<uint32_t*>(&o3);
        *reinterpret_cast<uint4*>(&row[c0]) = o;
    }
}

// ---------------- Fused residual-add + LayerNorm (192 thr, vectorized) ------
// X residual fp32; Hh (GEMM output) fp16.
__global__ void add_ln(const float* __restrict__ X, const __half* __restrict__ Hh,
                       const float* __restrict__ g, const float* __restrict__ b,
                       float* __restrict__ Y, __half* __restrict__ Yh)
{
    long long row = blockIdx.x;
    const float* x = X + row * EE;
    const __half* h = Hh + row * EE;
    float* y = Y + row * EE;
    int c = threadIdx.x * 4;

    float4 xv = *reinterpret_cast<const float4*>(&x[c]);
    uint2 hu = *reinterpret_cast<const uint2*>(&h[c]);
    float2 h0 = __half22float2(*reinterpret_cast<__half2*>(&hu.x));
    float2 h1 = __half22float2(*reinterpret_cast<__half2*>(&hu.y));
    float v[4] = {xv.x + h0.x, xv.y + h0.y, xv.z + h1.x, xv.w + h1.y};

    float s = v[0] + v[1] + v[2] + v[3];
    s = blockSum(s);
    float mean = s * (1.0f / EE);

    float q = 0.f;
    #pragma unroll
    for (int j = 0; j < 4; j++) { float d = v[j] - mean; q += d * d; }
    q = blockSum(q);
    float inv = rsqrtf(q * (1.0f / EE) + LN_EPS);

    float4 gv = *reinterpret_cast<const float4*>(&g[c]);
    float4 bv = *reinterpret_cast<const float4*>(&b[c]);
    float o[4];
    o[0] = (v[0] - mean) * inv * gv.x + bv.x;
    o[1] = (v[1] - mean) * inv * gv.y + bv.y;
    o[2] = (v[2] - mean) * inv * gv.z + bv.z;
    o[3] = (v[3] - mean) * inv * gv.w + bv.w;
    *reinterpret_cast<float4*>(&y[c]) = make_float4(o[0], o[1], o[2], o[3]);
    if (Yh) {
        __half2 q0 = __floats2half2_rn(o[0], o[1]);
        __half2 q1 = __floats2half2_rn(o[2], o[3]);
        uint2 u;
        u.x = *reinterpret_cast<uint32_t*>(&q0);
        u.y = *reinterpret_cast<uint32_t*>(&q1);
        *reinterpret_cast<uint2*>(&Yh[row * EE + c]) = u;
    }
}

// ---------------- Orchestration ----------------
extern "C" void kernel_launch(void* const* d_in, const int* in_sizes, int n_in,
                              void* d_out, int out_size)
{
    const float* x     = (const float*)d_in[0];
    const float* kv    = (const float*)d_in[1];
    const float* wq_w  = (const float*)d_in[2];
    const float* wq_b  = (const float*)d_in[3];
    const float* wk_w  = (const float*)d_in[4];
    const float* wk_b  = (const float*)d_in[5];
    const float* wv_w  = (const float*)d_in[6];
    const float* wv_b  = (const float*)d_in[7];
    const float* ln1_g = (const float*)d_in[8];
    const float* ln1_b = (const float*)d_in[9];
    const float* wq2_w = (const float*)d_in[10];
    const float* wq2_b = (const float*)d_in[11];
    const float* wk2_w = (const float*)d_in[12];
    const float* wk2_b = (const float*)d_in[13];
    const float* wv2_w = (const float*)d_in[14];
    const float* wv2_b = (const float*)d_in[15];
    const float* ln2_g = (const float*)d_in[16];
    const float* ln2_b = (const float*)d_in[17];
    const float* mlp_w1= (const float*)d_in[18];
    const float* mlp_b1= (const float*)d_in[19];
    const float* mlp_w2= (const float*)d_in[20];
    const float* mlp_b2= (const float*)d_in[21];
    const float* ln3_g = (const float*)d_in[22];
    const float* ln3_b = (const float*)d_in[23];
    float* out = (float*)d_out;

    __half *qkv, *x16, *kv16, *x1h, *x2h, *hh16, *p16, *t16, *wt;
    float *x1, *x2;
    cudaGetSymbolAddress((void**)&qkv,  g_qkv16);
    cudaGetSymbolAddress((void**)&x16,  g_x16);
    cudaGetSymbolAddress((void**)&kv16, g_kv16);
    cudaGetSymbolAddress((void**)&x1h,  g_x1h);
    cudaGetSymbolAddress((void**)&x2h,  g_x2h);
    cudaGetSymbolAddress((void**)&hh16, g_hh16);
    cudaGetSymbolAddress((void**)&p16,  g_p16);
    cudaGetSymbolAddress((void**)&t16,  g_t16);
    cudaGetSymbolAddress((void**)&wt,   g_wt16);
    cudaGetSymbolAddress((void**)&x1,   g_x1);
    cudaGetSymbolAddress((void**)&x2,   g_x2);

    cudaFuncSetAttribute(hgemm_k<0,1>, cudaFuncAttributeMaxDynamicSharedMemorySize, DSM);
    cudaFuncSetAttribute(hgemm_k<1,1>, cudaFuncAttributeMaxDynamicSharedMemorySize, DSM);
    cudaFuncSetAttribute(hg_proj5,     cudaFuncAttributeMaxDynamicSharedMemorySize, DSM);

    __half* q16 = qkv;
    __half* k16 = qkv + 1LL*MM*EE;
    __half* v16 = qkv + 2LL*MM*EE;
    __half* k2  = qkv + 3LL*MM*EE;
    __half* v2  = qkv + 4LL*MM*EE;
    __half* wq2T = wt + 5LL*EE*EE;
    __half* w1T  = wt + 6LL*EE*EE;
    __half* w2T  = wt + 6LL*EE*EE + (long long)EE*HH;

    const float scale = 1.0f / sqrtf((float)EE);
    const long long SE  = (long long)SS * EE;
    const long long SSS = (long long)SS * SS;

    dim3 b256(256), b192(192);
    dim3 gProj(EE / 128, MM / 128, 1);       // (6,128)
    dim3 gProj5(EE / 128, MM / 128, 5);      // (6,128,5)
    dim3 gScore(SS / 128, SS / 128, BB);     // (16,16,8)
    dim3 gPV(EE / 128, SS / 128, BB);        // (6,16,8)
    dim3 gMlp1(HH / 128, MM / 128, 1);       // (24,128)
    dim3 gSm(SS, BB);
    dim3 gLn(MM);

    // --- one-time conversions ---
    int n4 = MM * EE / 4;
    cvt2_h<<<dim3((n4 + 255) / 256, 2), b256>>>((const float4*)x, (const float4*)kv,
                                                (__half2*)x16, (__half2*)kv16, n4);
    transp6_h<<<dim3(24, 24, 6), b256>>>(wq_w, wk_w, wv_w, wk2_w, wv2_w, wq2_w, wt);
    transp_h<<<dim3(EE/32, HH/32), b256>>>(mlp_w1, w1T, EE, HH);
    transp_h<<<dim3(HH/32, EE/32), b256>>>(mlp_w2, w2T, HH, EE);

    // --- all 5 input projections in one launch ---
    hg_proj5<<<gProj5, b256, DSM>>>(x16, kv16, wt, wq_b, wk_b, wv_b, wk2_b, wv2_b, qkv);

    // --- causal self-attention (fp16 end-to-end intermediates) ---
    hgemm_k<0,1><<<gScore, b256, DSM>>>(q16, k16, nullptr, p16, SS, EE,
                                        SE, SE, SSS, scale, 0, 1, 0);
    softmax16<<<gSm, b256>>>(p16, SS, 1);
    hgemm_k<1,1><<<gPV, b256, DSM>>>(p16, v16, nullptr, t16, EE, SS,
                                     SSS, SE, SE, 1.0f, 0, 0, 1);
    add_ln<<<gLn, b192>>>(x, t16, ln1_g, ln1_b, x1, x1h);

    // --- cross-attention ---
    hgemm_k<0,1><<<gProj, b256, DSM>>>(x1h, wq2T, wq2_b, q16, EE, EE,
                                       0, 0, 0, 1.0f, 0, 0, 0);
    hgemm_k<0,1><<<gScore, b256, DSM>>>(q16, k2, nullptr, p16, SS, EE,
                                        SE, SE, SSS, scale, 0, 0, 0);
    softmax16<<<gSm, b256>>>(p16, SS, 0);
    hgemm_k<1,1><<<gPV, b256, DSM>>>(p16, v2, nullptr, t16, EE, SS,
                                     SSS, SE, SE, 1.0f, 0, 0, 0);
    add_ln<<<gLn, b192>>>(x1, t16, ln2_g, ln2_b, x2, x2h);

    // --- MLP (ReLU after both linears) ---
    hgemm_k<0,1><<<gMlp1, b256, DSM>>>(x2h, w1T, mlp_b1, hh16, HH, EE,
                                       0, 0, 0, 1.0f, 1, 0, 0);
    hgemm_k<0,1><<<gProj, b256, DSM>>>(hh16, w2T, mlp_b2, t16, EE, HH,
                                       0, 0, 0, 1.0f, 1, 0, 0);
    add_ln<<<gLn, b192>>>(x2, t16, ln3_g, ln3_b, out, nullptr);
}